// round 13
// baseline (speedup 1.0000x reference)
#include <cuda_runtime.h>
#include <math.h>

#define B_ 128
#define S_ 1024
#define I_ 512
#define H_ 1024
#define O_ 512
#define HP 36          // hs row pitch (floats): conflict-free staging + reads

static __device__ float    g_xpT[(size_t)S_ * H_ * B_];  // [s][h][b]
static __device__ float    g_h[2 * H_ * B_];             // [buf][k][b]
static __device__ unsigned g_tick[4];                    // monotonic ticket barriers

// ---------------------------------------------------------------------------
// Phase 1: xpT[s][h][b] = sum_i x[b][s][i]*W_ih[h][i] + b_ih[h] + b_hh[h]
// grid (8 h-tiles, 1024 s), 256 threads, 8x8 microtile, 128h x 128b per CTA.
// ---------------------------------------------------------------------------
__global__ void __launch_bounds__(256) xpT_gemm(const float* __restrict__ x,
                                                const float* __restrict__ W_ih,
                                                const float* __restrict__ b_ih,
                                                const float* __restrict__ b_hh) {
    __shared__ float As[8][132];   // [i][h]
    __shared__ float Bs[8][132];   // [i][b]
    const int s    = blockIdx.y;
    const int h0   = blockIdx.x * 128;
    const int tid  = threadIdx.x;
    const int row  = tid >> 1;          // 0..127
    const int iseg = (tid & 1) << 2;    // 0 or 4
    const int tx   = tid & 15;          // b microtile
    const int ty   = tid >> 4;          // h microtile

    const float* Ag = W_ih + (size_t)(h0 + row) * I_ + iseg;
    const float* Bg = x + ((size_t)row * S_ + s) * I_ + iseg;

    float acc[8][8];
#pragma unroll
    for (int u = 0; u < 8; u++)
#pragma unroll
        for (int v = 0; v < 8; v++) acc[u][v] = 0.f;

    float4 ra = *(const float4*)Ag;
    float4 rb = *(const float4*)Bg;

    for (int ic = 0; ic < I_; ic += 8) {
        if (ic) __syncthreads();
        As[iseg + 0][row] = ra.x; As[iseg + 1][row] = ra.y;
        As[iseg + 2][row] = ra.z; As[iseg + 3][row] = ra.w;
        Bs[iseg + 0][row] = rb.x; Bs[iseg + 1][row] = rb.y;
        Bs[iseg + 2][row] = rb.z; Bs[iseg + 3][row] = rb.w;
        if (ic + 8 < I_) {
            ra = *(const float4*)(Ag + ic + 8);
            rb = *(const float4*)(Bg + ic + 8);
        }
        __syncthreads();
#pragma unroll
        for (int i = 0; i < 8; i++) {
            float a[8], b[8];
            *(float4*)&a[0] = *(const float4*)&As[i][ty * 8];
            *(float4*)&a[4] = *(const float4*)&As[i][ty * 8 + 4];
            *(float4*)&b[0] = *(const float4*)&Bs[i][tx * 8];
            *(float4*)&b[4] = *(const float4*)&Bs[i][tx * 8 + 4];
#pragma unroll
            for (int u = 0; u < 8; u++)
#pragma unroll
                for (int v = 0; v < 8; v++)
                    acc[u][v] = fmaf(a[u], b[v], acc[u][v]);
        }
    }
#pragma unroll
    for (int u = 0; u < 8; u++) {
        const int h = h0 + ty * 8 + u;
        const float bias = __ldg(&b_ih[h]) + __ldg(&b_hh[h]);
        float* dst = g_xpT + ((size_t)s * H_ + h) * B_ + tx * 8;
        float4 o0 = {acc[u][0] + bias, acc[u][1] + bias, acc[u][2] + bias, acc[u][3] + bias};
        float4 o1 = {acc[u][4] + bias, acc[u][5] + bias, acc[u][6] + bias, acc[u][7] + bias};
        *(float4*)dst = o0;
        *(float4*)(dst + 4) = o1;
    }
}

// ---------------------------------------------------------------------------
// Ticket barrier among 32 CTAs of one batch group. Monotonic: no reset, safe
// across graph replays. Consumer-side __threadfence() invalidates L1D
// (CCTL.IVALL at gpu-scope fence) so post-barrier plain loads see peer writes.
// ---------------------------------------------------------------------------
__device__ __forceinline__ void group_barrier(unsigned* t) {
    __threadfence();
    __syncthreads();
    if (threadIdx.x == 0) {
        const unsigned my = atomicAdd(t, 1u);
        const unsigned target = ((my >> 5) + 1u) << 5;   // 32 arrivals/generation
        volatile unsigned* vt = t;
        while (*vt < target) { }
        __threadfence();
    }
    __syncthreads();
}

// ---------------------------------------------------------------------------
// Phase 2: persistent scan. CTA c: gi=c>>5 (batch block of 32), jt=c&31
// (32 output rows). Warp = 4 j-rows x 32 batches(lanes). W_hh slice in smem
// for all steps; h staged through smem in 64-k chunks with LDG prefetch.
// ---------------------------------------------------------------------------
__global__ void __launch_bounds__(256, 1) rnn_scan(const float* __restrict__ W_hh) {
    extern __shared__ float sm[];
    float* Wsm = sm;                  // [32][1024]
    float* hs  = sm + 32 * H_;        // [64][HP]

    const int tid  = threadIdx.x;
    const int c    = blockIdx.x;
    const int gi   = c >> 5;
    const int jt   = c & 31;
    const int j0   = jt << 5;
    const int b0   = gi << 5;
    const int w    = tid >> 5;
    const int lane = tid & 31;
    const int jl   = w << 2;
    const int jw   = j0 + jl;

    {   // W_hh rows j0..j0+31 -> smem (once)
        const float4* Wg = (const float4*)(W_hh + (size_t)j0 * H_);
        float4* Wl = (float4*)Wsm;
        for (int i = tid; i < 32 * (H_ / 4); i += 256) Wl[i] = Wg[i];
    }
    {   // zero h buf0: rows [jt*32,+32), cols [b0,+32)
        const int kz = jt << 5;
        for (int i = tid; i < 32 * 32; i += 256)
            g_h[(size_t)(kz + (i >> 5)) * B_ + b0 + (i & 31)] = 0.f;
    }
    group_barrier(&g_tick[gi]);

    const int sk = tid >> 2;            // staging k row 0..63
    const int sb = (tid & 3) << 3;      // staging 8-float b segment
    const float* w0p = Wsm + (size_t)(jl + 0) * H_;
    const float* w1p = Wsm + (size_t)(jl + 1) * H_;
    const float* w2p = Wsm + (size_t)(jl + 2) * H_;
    const float* w3p = Wsm + (size_t)(jl + 3) * H_;

    for (int t = 0; t < S_; ++t) {
        const float* hin  = g_h + (size_t)(t & 1) * (H_ * B_);
        float*       hout = g_h + (size_t)((t + 1) & 1) * (H_ * B_);
        const float* hbase = hin + (size_t)sk * B_ + b0 + sb;

        const float* xpp = g_xpT + ((size_t)t * H_ + jw) * B_ + b0 + lane;
        const float xv0 = __ldg(xpp);
        const float xv1 = __ldg(xpp + B_);
        const float xv2 = __ldg(xpp + 2 * B_);
        const float xv3 = __ldg(xpp + 3 * B_);

        float a0 = 0.f, a1 = 0.f, a2 = 0.f, a3 = 0.f;
        float4 p0 = *(const float4*)hbase;
        float4 p1 = *(const float4*)(hbase + 4);

        for (int cch = 0; cch < 16; ++cch) {
            __syncthreads();
            *(float4*)(hs + sk * HP + sb)     = p0;
            *(float4*)(hs + sk * HP + sb + 4) = p1;
            if (cch < 15) {
                const float* nx = hbase + (size_t)(cch + 1) * 64 * B_;
                p0 = *(const float4*)nx;
                p1 = *(const float4*)(nx + 4);
            }
            __syncthreads();
            const int kk0 = cch << 6;
#pragma unroll 4
            for (int k = 0; k < 64; k += 4) {
                const int kk = kk0 + k;
                const float4 w0 = *(const float4*)(w0p + kk);
                const float4 w1 = *(const float4*)(w1p + kk);
                const float4 w2 = *(const float4*)(w2p + kk);
                const float4 w3 = *(const float4*)(w3p + kk);
                const float* hp = hs + k * HP + lane;
                const float h0 = hp[0], h1 = hp[HP], h2 = hp[2 * HP], h3 = hp[3 * HP];
                a0 = fmaf(w0.x, h0, a0); a1 = fmaf(w1.x, h0, a1);
                a2 = fmaf(w2.x, h0, a2); a3 = fmaf(w3.x, h0, a3);
                a0 = fmaf(w0.y, h1, a0); a1 = fmaf(w1.y, h1, a1);
                a2 = fmaf(w2.y, h1, a2); a3 = fmaf(w3.y, h1, a3);
                a0 = fmaf(w0.z, h2, a0); a1 = fmaf(w1.z, h2, a1);
                a2 = fmaf(w2.z, h2, a2); a3 = fmaf(w3.z, h2, a3);
                a0 = fmaf(w0.w, h3, a0); a1 = fmaf(w1.w, h3, a1);
                a2 = fmaf(w2.w, h3, a2); a3 = fmaf(w3.w, h3, a3);
            }
        }
        hout[(size_t)(jw + 0) * B_ + b0 + lane] = tanhf(a0 + xv0);
        hout[(size_t)(jw + 1) * B_ + b0 + lane] = tanhf(a1 + xv1);
        hout[(size_t)(jw + 2) * B_ + b0 + lane] = tanhf(a2 + xv2);
        hout[(size_t)(jw + 3) * B_ + b0 + lane] = tanhf(a3 + xv3);

        group_barrier(&g_tick[gi]);
    }
}

// ---------------------------------------------------------------------------
// Phase 3: out[b][o] = sum_k hT[k][b]*W_fc[o][k] + b_fc[o].  hT = g_h buf0
// (S even). grid 512 (o), 128 threads (b): h loads coalesced, W broadcast.
// ---------------------------------------------------------------------------
__global__ void __launch_bounds__(128) fc_kernel(const float* __restrict__ W_fc,
                                                 const float* __restrict__ b_fc,
                                                 float* __restrict__ out) {
    const int o = blockIdx.x;
    const int b = threadIdx.x;
    const float* h = g_h;   // buf 0
    const float* wr = W_fc + (size_t)o * H_;
    float s = 0.f;
#pragma unroll 4
    for (int k = 0; k < H_; k += 4) {
        const float4 wv = __ldg((const float4*)(wr + k));
        s = fmaf(wv.x, h[(size_t)(k + 0) * B_ + b], s);
        s = fmaf(wv.y, h[(size_t)(k + 1) * B_ + b], s);
        s = fmaf(wv.z, h[(size_t)(k + 2) * B_ + b], s);
        s = fmaf(wv.w, h[(size_t)(k + 3) * B_ + b], s);
    }
    out[(size_t)b * O_ + o] = s + __ldg(&b_fc[o]);
}

extern "C" void kernel_launch(void* const* d_in, const int* in_sizes, int n_in,
                              void* d_out, int out_size) {
    const float* x    = (const float*)d_in[0];
    const float* W_ih = (const float*)d_in[1];
    const float* W_hh = (const float*)d_in[2];
    const float* b_ih = (const float*)d_in[3];
    const float* b_hh = (const float*)d_in[4];
    const float* W_fc = (const float*)d_in[5];
    const float* b_fc = (const float*)d_in[6];
    float* out = (float*)d_out;

    xpT_gemm<<<dim3(8, 1024), 256>>>(x, W_ih, b_ih, b_hh);

    const int smem2 = (32 * H_ + 64 * HP) * (int)sizeof(float);
    cudaFuncSetAttribute(rnn_scan, cudaFuncAttributeMaxDynamicSharedMemorySize, smem2);
    rnn_scan<<<128, 256, smem2>>>(W_hh);

    fc_kernel<<<O_, B_>>>(W_fc, b_fc, out);
}

// round 14
// speedup vs baseline: 1.2073x; 1.2073x over previous
#include <cuda_runtime.h>
#include <math.h>

#define B_ 128
#define S_ 1024
#define I_ 512
#define H_ 1024
#define O_ 512
#define WPITCH 1028      // W smem row pitch (floats): j-row stride mod 32 = 4 -> conflict-free

static __device__ float    g_xpT[(size_t)S_ * H_ * B_];  // [s][h][b]
static __device__ float    g_h[2 * H_ * B_];             // [buf][k][b]
static __device__ unsigned g_tick[4];                    // monotonic ticket barriers

// ---------------------------------------------------------------------------
// Phase 1: xpT[s][h][b] = sum_i x[b][s][i]*W_ih[h][i] + b_ih[h] + b_hh[h]
// grid (8 h-tiles, 1024 s), 256 thr, 8x8 microtile, double-buffered smem
// (one __syncthreads per 8-k chunk).
// ---------------------------------------------------------------------------
__global__ void __launch_bounds__(256) xpT_gemm(const float* __restrict__ x,
                                                const float* __restrict__ W_ih,
                                                const float* __restrict__ b_ih,
                                                const float* __restrict__ b_hh) {
    __shared__ float As[2][8][132];   // [buf][i][h]
    __shared__ float Bs[2][8][132];   // [buf][i][b]
    const int s    = blockIdx.y;
    const int h0   = blockIdx.x * 128;
    const int tid  = threadIdx.x;
    const int row  = tid >> 1;          // 0..127
    const int iseg = (tid & 1) << 2;    // 0 or 4
    const int tx   = tid & 15;          // b microtile
    const int ty   = tid >> 4;          // h microtile

    const float* Ag = W_ih + (size_t)(h0 + row) * I_ + iseg;
    const float* Bg = x + ((size_t)row * S_ + s) * I_ + iseg;

    float acc[8][8];
#pragma unroll
    for (int u = 0; u < 8; u++)
#pragma unroll
        for (int v = 0; v < 8; v++) acc[u][v] = 0.f;

    float4 ra = *(const float4*)Ag;
    float4 rb = *(const float4*)Bg;
    int cur = 0;

    for (int ic = 0; ic < I_; ic += 8) {
        As[cur][iseg + 0][row] = ra.x; As[cur][iseg + 1][row] = ra.y;
        As[cur][iseg + 2][row] = ra.z; As[cur][iseg + 3][row] = ra.w;
        Bs[cur][iseg + 0][row] = rb.x; Bs[cur][iseg + 1][row] = rb.y;
        Bs[cur][iseg + 2][row] = rb.z; Bs[cur][iseg + 3][row] = rb.w;
        __syncthreads();
        if (ic + 8 < I_) {
            ra = *(const float4*)(Ag + ic + 8);
            rb = *(const float4*)(Bg + ic + 8);
        }
#pragma unroll
        for (int i = 0; i < 8; i++) {
            float a[8], b[8];
            *(float4*)&a[0] = *(const float4*)&As[cur][i][ty * 8];
            *(float4*)&a[4] = *(const float4*)&As[cur][i][ty * 8 + 4];
            *(float4*)&b[0] = *(const float4*)&Bs[cur][i][tx * 8];
            *(float4*)&b[4] = *(const float4*)&Bs[cur][i][tx * 8 + 4];
#pragma unroll
            for (int u = 0; u < 8; u++)
#pragma unroll
                for (int v = 0; v < 8; v++)
                    acc[u][v] = fmaf(a[u], b[v], acc[u][v]);
        }
        cur ^= 1;
    }
#pragma unroll
    for (int u = 0; u < 8; u++) {
        const int h = h0 + ty * 8 + u;
        const float bias = __ldg(&b_ih[h]) + __ldg(&b_hh[h]);
        float* dst = g_xpT + ((size_t)s * H_ + h) * B_ + tx * 8;
        float4 o0 = {acc[u][0] + bias, acc[u][1] + bias, acc[u][2] + bias, acc[u][3] + bias};
        float4 o1 = {acc[u][4] + bias, acc[u][5] + bias, acc[u][6] + bias, acc[u][7] + bias};
        *(float4*)dst = o0;
        *(float4*)(dst + 4) = o1;
    }
}

// ---------------------------------------------------------------------------
// Ticket barrier among 32 CTAs of one batch group. Monotonic counter: no
// reset, correct across graph replays. Post-spin __threadfence() (gpu scope
// -> CCTL.IVALL) invalidates L1D so post-barrier loads see peer SM writes.
// ---------------------------------------------------------------------------
__device__ __forceinline__ void group_barrier(unsigned* t) {
    __threadfence();
    __syncthreads();
    if (threadIdx.x == 0) {
        const unsigned my = atomicAdd(t, 1u);
        const unsigned target = ((my >> 5) + 1u) << 5;   // 32 arrivals/generation
        volatile unsigned* vt = t;
        while (*vt < target) { }
        __threadfence();
    }
    __syncthreads();
}

// ---------------------------------------------------------------------------
// Phase 2: persistent scan, 128 CTAs x 128 threads (4 warps).
// CTA c: gi=c>>5 (batch block of 32), jt=c&31 (32 output rows).
// Warp w: j rows [j0+8w, +8). Thread (jp=lane>>3, bq=lane&7): 2 j x 4 b.
// Per 4-k group/thread: 32 FMA, 6 LDS.128 (2 W broadcast + 4 h) -> FFMA-bound.
// W_hh slice pinned in smem (pitched); h staged [64k][32b] with LDG prefetch.
// ---------------------------------------------------------------------------
__global__ void __launch_bounds__(128, 1) rnn_scan(const float* __restrict__ W_hh) {
    extern __shared__ float sm[];
    float* Wsm = sm;                      // [32][WPITCH]
    float* hs  = sm + 32 * WPITCH;        // [64][32]

    const int tid  = threadIdx.x;
    const int c    = blockIdx.x;
    const int gi   = c >> 5;
    const int jt   = c & 31;
    const int j0   = jt << 5;
    const int b0   = gi << 5;
    const int w    = tid >> 5;
    const int lane = tid & 31;
    const int jp   = lane >> 3;           // 0..3
    const int bq   = lane & 7;            // 0..7
    const int jA   = (w << 3) + (jp << 1);
    const int jgA  = j0 + jA;

    {   // W_hh rows j0..j0+31 -> pitched smem (once)
        for (int r = w; r < 32; r += 4) {
            const float4* src = (const float4*)(W_hh + (size_t)(j0 + r) * H_);
            float4* dst = (float4*)(Wsm + r * WPITCH);
            for (int i = lane; i < H_ / 4; i += 32) dst[i] = src[i];
        }
    }
    {   // zero h buf0: rows [jt*32,+32), cols [b0,+32)
        const int kz = jt << 5;
        for (int i = tid; i < 1024; i += 128)
            g_h[(size_t)(kz + (i >> 5)) * B_ + b0 + (i & 31)] = 0.f;
    }
    group_barrier(&g_tick[gi]);

    const float* wAp = Wsm + (size_t)jA * WPITCH;
    const float* wBp = wAp + WPITCH;
    const int hsoff = bq << 2;
    const int k0s = tid >> 3;             // staging k row 0..15 (+16/32/48)
    const int c0s = tid & 7;              // staging f4 col 0..7

    for (int t = 0; t < S_; ++t) {
        const float*  hin  = g_h + (size_t)(t & 1) * (H_ * B_);
        float*        hout = g_h + (size_t)((t + 1) & 1) * (H_ * B_);
        const float4* hin4 = (const float4*)hin + (b0 >> 2);   // row = 32 f4

        // xp prefetch: 2 rows x 4 b (coalesced 128B per jp row)
        const float* xpp = g_xpT + ((size_t)t * H_ + jgA) * B_ + b0 + hsoff;
        const float4 xa = __ldg((const float4*)xpp);
        const float4 xb = __ldg((const float4*)(xpp + B_));

        float4 aA = {0.f, 0.f, 0.f, 0.f};
        float4 aB = {0.f, 0.f, 0.f, 0.f};

        float4 p0 = hin4[(size_t)(k0s)      * 32 + c0s];
        float4 p1 = hin4[(size_t)(k0s + 16) * 32 + c0s];
        float4 p2 = hin4[(size_t)(k0s + 32) * 32 + c0s];
        float4 p3 = hin4[(size_t)(k0s + 48) * 32 + c0s];

        for (int ch = 0; ch < 16; ++ch) {
            __syncthreads();
            float4* hs4 = (float4*)hs;
            hs4[(k0s)      * 8 + c0s] = p0;
            hs4[(k0s + 16) * 8 + c0s] = p1;
            hs4[(k0s + 32) * 8 + c0s] = p2;
            hs4[(k0s + 48) * 8 + c0s] = p3;
            if (ch < 15) {
                const float4* nb = hin4 + (size_t)(ch + 1) * 64 * 32;
                p0 = nb[(size_t)(k0s)      * 32 + c0s];
                p1 = nb[(size_t)(k0s + 16) * 32 + c0s];
                p2 = nb[(size_t)(k0s + 32) * 32 + c0s];
                p3 = nb[(size_t)(k0s + 48) * 32 + c0s];
            }
            __syncthreads();
            const float* wA = wAp + (ch << 6);
            const float* wB = wBp + (ch << 6);
#pragma unroll
            for (int k = 0; k < 64; k += 4) {
                const float4 wa = *(const float4*)(wA + k);
                const float4 wb = *(const float4*)(wB + k);
                const float* hp = hs + (k << 5) + hsoff;
                const float4 h0 = *(const float4*)(hp);
                const float4 h1 = *(const float4*)(hp + 32);
                const float4 h2 = *(const float4*)(hp + 64);
                const float4 h3 = *(const float4*)(hp + 96);
                aA.x = fmaf(wa.x, h0.x, aA.x); aA.y = fmaf(wa.x, h0.y, aA.y);
                aA.z = fmaf(wa.x, h0.z, aA.z); aA.w = fmaf(wa.x, h0.w, aA.w);
                aB.x = fmaf(wb.x, h0.x, aB.x); aB.y = fmaf(wb.x, h0.y, aB.y);
                aB.z = fmaf(wb.x, h0.z, aB.z); aB.w = fmaf(wb.x, h0.w, aB.w);
                aA.x = fmaf(wa.y, h1.x, aA.x); aA.y = fmaf(wa.y, h1.y, aA.y);
                aA.z = fmaf(wa.y, h1.z, aA.z); aA.w = fmaf(wa.y, h1.w, aA.w);
                aB.x = fmaf(wb.y, h1.x, aB.x); aB.y = fmaf(wb.y, h1.y, aB.y);
                aB.z = fmaf(wb.y, h1.z, aB.z); aB.w = fmaf(wb.y, h1.w, aB.w);
                aA.x = fmaf(wa.z, h2.x, aA.x); aA.y = fmaf(wa.z, h2.y, aA.y);
                aA.z = fmaf(wa.z, h2.z, aA.z); aA.w = fmaf(wa.z, h2.w, aA.w);
                aB.x = fmaf(wb.z, h2.x, aB.x); aB.y = fmaf(wb.z, h2.y, aB.y);
                aB.z = fmaf(wb.z, h2.z, aB.z); aB.w = fmaf(wb.z, h2.w, aB.w);
                aA.x = fmaf(wa.w, h3.x, aA.x); aA.y = fmaf(wa.w, h3.y, aA.y);
                aA.z = fmaf(wa.w, h3.z, aA.z); aA.w = fmaf(wa.w, h3.w, aA.w);
                aB.x = fmaf(wb.w, h3.x, aB.x); aB.y = fmaf(wb.w, h3.y, aB.y);
                aB.z = fmaf(wb.w, h3.z, aB.z); aB.w = fmaf(wb.w, h3.w, aB.w);
            }
        }
        float4 oA, oB;
        oA.x = tanhf(aA.x + xa.x); oA.y = tanhf(aA.y + xa.y);
        oA.z = tanhf(aA.z + xa.z); oA.w = tanhf(aA.w + xa.w);
        oB.x = tanhf(aB.x + xb.x); oB.y = tanhf(aB.y + xb.y);
        oB.z = tanhf(aB.z + xb.z); oB.w = tanhf(aB.w + xb.w);
        float* dA = hout + (size_t)jgA * B_ + b0 + hsoff;
        *(float4*)dA        = oA;
        *(float4*)(dA + B_) = oB;

        group_barrier(&g_tick[gi]);
    }
}

// ---------------------------------------------------------------------------
// Phase 3: out[b][o] = sum_k hT[k][b]*W_fc[o][k] + b_fc[o].  hT = g_h buf0.
// ---------------------------------------------------------------------------
__global__ void __launch_bounds__(128) fc_kernel(const float* __restrict__ W_fc,
                                                 const float* __restrict__ b_fc,
                                                 float* __restrict__ out) {
    const int o = blockIdx.x;
    const int b = threadIdx.x;
    const float* h = g_h;   // buf 0 (S even)
    const float* wr = W_fc + (size_t)o * H_;
    float s = 0.f;
#pragma unroll 4
    for (int k = 0; k < H_; k += 4) {
        const float4 wv = __ldg((const float4*)(wr + k));
        s = fmaf(wv.x, h[(size_t)(k + 0) * B_ + b], s);
        s = fmaf(wv.y, h[(size_t)(k + 1) * B_ + b], s);
        s = fmaf(wv.z, h[(size_t)(k + 2) * B_ + b], s);
        s = fmaf(wv.w, h[(size_t)(k + 3) * B_ + b], s);
    }
    out[(size_t)b * O_ + o] = s + __ldg(&b_fc[o]);
}

extern "C" void kernel_launch(void* const* d_in, const int* in_sizes, int n_in,
                              void* d_out, int out_size) {
    const float* x    = (const float*)d_in[0];
    const float* W_ih = (const float*)d_in[1];
    const float* W_hh = (const float*)d_in[2];
    const float* b_ih = (const float*)d_in[3];
    const float* b_hh = (const float*)d_in[4];
    const float* W_fc = (const float*)d_in[5];
    const float* b_fc = (const float*)d_in[6];
    float* out = (float*)d_out;

    xpT_gemm<<<dim3(8, 1024), 256>>>(x, W_ih, b_ih, b_hh);

    const int smem2 = (32 * WPITCH + 64 * 32) * (int)sizeof(float);
    cudaFuncSetAttribute(rnn_scan, cudaFuncAttributeMaxDynamicSharedMemorySize, smem2);
    rnn_scan<<<128, 128, smem2>>>(W_hh);

    fc_kernel<<<O_, B_>>>(W_fc, b_fc, out);
}